// round 12
// baseline (speedup 1.0000x reference)
#include <cuda_runtime.h>
#include <cuda_bf16.h>

#define NN 50000
#define NE 800000
#define NG 512
#define DN 64
#define DE 32
#define ET 128               // edges per tile
#define NTILES (NE / ET)     // 6250
#define EGRID 296            // persistent blocks (148 SMs x 2)

// Scratch (allocation-free: __device__ globals)
__device__ float g_ABd[NN * 128];
__device__ float g_ABs[NN * 128];
__device__ float g_h1[NN * DN];
__device__ float g_h2[NN * DN];

// ---------------------------------------------------------------------------
// Node projection into interleaved gather layout (+ bias fold).
// ---------------------------------------------------------------------------
__global__ void __launch_bounds__(256) proj_kernel(
    const float* __restrict__ h, const float* __restrict__ Wf,
    const float* __restrict__ Ws, const float* __restrict__ bfv,
    const float* __restrict__ bsv, float* __restrict__ ABd,
    float* __restrict__ ABs)
{
    __shared__ float As[64][65];
    __shared__ float Bs[64][64];

    const int tid = threadIdx.x;
    const int node0 = blockIdx.x * 64;
    const int cb = blockIdx.y;

    const float* Wsrc = (cb < 2) ? Wf : Ws;
    const int rowoff = (cb & 1) ? 64 : 0;

#pragma unroll
    for (int t = 0; t < 16; t++) {
        int lin = t * 256 + tid;
        int k = lin >> 6, j = lin & 63;
        Bs[k][j] = Wsrc[(rowoff + k) * 64 + j];
    }
#pragma unroll
    for (int t = 0; t < 16; t++) {
        int lin = t * 256 + tid;
        int n = lin >> 6, k = lin & 63;
        int node = node0 + n;
        As[k][n] = (node < NN) ? h[node * 64 + k] : 0.0f;
    }
    __syncthreads();

    const int tx = tid & 15;
    const int ty = tid >> 4;
    float acc[4][4] = {};

#pragma unroll
    for (int k = 0; k < 64; k++) {
        float4 b4 = *(const float4*)&Bs[k][tx * 4];
        float a0 = As[k][ty * 4 + 0];
        float a1 = As[k][ty * 4 + 1];
        float a2 = As[k][ty * 4 + 2];
        float a3 = As[k][ty * 4 + 3];
        acc[0][0] += a0 * b4.x; acc[0][1] += a0 * b4.y; acc[0][2] += a0 * b4.z; acc[0][3] += a0 * b4.w;
        acc[1][0] += a1 * b4.x; acc[1][1] += a1 * b4.y; acc[1][2] += a1 * b4.z; acc[1][3] += a1 * b4.w;
        acc[2][0] += a2 * b4.x; acc[2][1] += a2 * b4.y; acc[2][2] += a2 * b4.z; acc[2][3] += a2 * b4.w;
        acc[3][0] += a3 * b4.x; acc[3][1] += a3 * b4.y; acc[3][2] += a3 * b4.z; acc[3][3] += a3 * b4.w;
    }

    float bias[4] = {0.f, 0.f, 0.f, 0.f};
    if (cb == 0) {
#pragma unroll
        for (int j = 0; j < 4; j++) bias[j] = bfv[tx * 4 + j];
    } else if (cb == 2) {
#pragma unroll
        for (int j = 0; j < 4; j++) bias[j] = bsv[tx * 4 + j];
    }

    float* outbase = (cb == 0 || cb == 2) ? ABd : ABs;
    const int sub = (cb >= 2) ? 2 : 0;

#pragma unroll
    for (int i = 0; i < 4; i++) {
        int node = node0 + ty * 4 + i;
        if (node < NN) {
            float2 lo = make_float2(acc[i][0] + bias[0], acc[i][1] + bias[1]);
            float2 hi = make_float2(acc[i][2] + bias[2], acc[i][3] + bias[3]);
            *(float2*)&outbase[(size_t)node * 128 + (2 * tx + 0) * 4 + sub] = lo;
            *(float2*)&outbase[(size_t)node * 128 + (2 * tx + 1) * 4 + sub] = hi;
        }
    }
}

// ---------------------------------------------------------------------------
// Persistent edge GEMM: 296 blocks x ~21 tiles. Weights staged once/block.
// Next tile's ea + indices prefetched via cp.async (raw buffer) during the
// current k-loop; smem->smem transform builds duplicated {e,e} layout.
// ---------------------------------------------------------------------------
__device__ __forceinline__ float sigmoidf_(float x) {
    return 1.0f / (1.0f + __expf(-x));
}
__device__ __forceinline__ float softplusf_(float x) {
    float ax = fabsf(x);
    float em = __expf(-ax);
    return fmaxf(x, 0.0f) + __logf(1.0f + em);
}

// Dynamic smem layout (floats):
//   Bq   [32][128]        @ 0       (16 KB)
//   Asd  [32][256]        @ 4096    (32 KB)
//   raw  [2][128*32]      @ 12288   (32 KB)
//   sidx [2][2][128] int  @ 20480   (2 KB)
#define SM_BQ   0
#define SM_ASD  4096
#define SM_RAW  12288
#define SM_SIDX 20480
#define EDGE_SMEM_FLOATS 20992
#define EDGE_SMEM_BYTES  (EDGE_SMEM_FLOATS * 4)

__global__ void __launch_bounds__(256, 2) edge_gemm_kernel(
    const int* __restrict__ ei, const float* __restrict__ ea,
    const float* __restrict__ ABd, const float* __restrict__ ABs,
    const float* __restrict__ Wf, const float* __restrict__ Ws,
    float* __restrict__ hout)
{
    extern __shared__ float smem[];
    float* Bq  = smem + SM_BQ;
    float* Asd = smem + SM_ASD;
    float* raw = smem + SM_RAW;
    int*   sidx = (int*)(smem + SM_SIDX);

    const int tid = threadIdx.x;

    // --- Prologue: issue cp.async for first tile into buffer 0 ---
    {
        int e0 = blockIdx.x * ET;
        unsigned di = (unsigned)__cvta_generic_to_shared(&sidx[tid]);
        const int* gi = (tid < 128) ? (ei + e0 + tid) : (ei + NE + e0 + (tid - 128));
        asm volatile("cp.async.ca.shared.global [%0], [%1], 4;" :: "r"(di), "l"(gi));
#pragma unroll
        for (int q = 0; q < 4; q++) {
            int c = tid + 256 * q;             // 1024 chunks of 16B
            int edge = c >> 3, k4 = c & 7;
            const float* g = ea + (size_t)(e0 + edge) * 32 + k4 * 4;
            unsigned dr = (unsigned)__cvta_generic_to_shared(&raw[edge * 32 + k4 * 4]);
            asm volatile("cp.async.ca.shared.global [%0], [%1], 16;" :: "r"(dr), "l"(g));
        }
        asm volatile("cp.async.commit_group;");
    }

    // --- Stage quad-interleaved bottom weights ONCE per block ---
#pragma unroll
    for (int q = 0; q < 16; q++) {
        int idx = q * 256 + tid;
        int k = idx >> 7, col = idx & 127;
        int c = col >> 2, sub = col & 3;
        const float* W = (sub < 2) ? Wf : Ws;
        Bq[k * 128 + col] = W[(size_t)(128 + k) * 64 + 2 * c + (sub & 1)];
    }

    const int qc = tid & 31;
    const int eg = tid >> 5;
    const unsigned abase = (unsigned)__cvta_generic_to_shared(&Asd[eg * 32]);
    const unsigned bbase = (unsigned)__cvta_generic_to_shared(&Bq[qc * 4]);

    int buf = 0;
    for (int t = blockIdx.x; t < NTILES; t += EGRID) {
        asm volatile("cp.async.wait_group 0;" ::: "memory");
        __syncthreads();   // raw[buf]+sidx[buf] landed; all warps past prev k-loop

        // --- Transform raw[buf] -> Asd (duplicated {e,e}) ---
        {
            const int el = tid >> 1, k0 = (tid & 1) * 16;
            const float* rp = &raw[buf * 4096 + el * 32 + k0];
#pragma unroll
            for (int q = 0; q < 4; q++) {
                float4 v = *(const float4*)(rp + q * 4);
#pragma unroll
                for (int j = 0; j < 4; j++) {
                    float x = (&v.x)[j];
                    *(float2*)&Asd[(k0 + q * 4 + j) * 256 + 2 * el] = make_float2(x, x);
                }
            }
        }
        __syncthreads();   // Asd visible

        // --- Prefetch next tile into the other buffer ---
        int tn = t + EGRID;
        if (tn < NTILES) {
            int e0n = tn * ET;
            int nb = buf ^ 1;
            unsigned di = (unsigned)__cvta_generic_to_shared(&sidx[nb * 256 + tid]);
            const int* gi = (tid < 128) ? (ei + e0n + tid)
                                        : (ei + NE + e0n + (tid - 128));
            asm volatile("cp.async.ca.shared.global [%0], [%1], 4;" :: "r"(di), "l"(gi));
#pragma unroll
            for (int q = 0; q < 4; q++) {
                int c = tid + 256 * q;
                int edge = c >> 3, k4 = c & 7;
                const float* g = ea + (size_t)(e0n + edge) * 32 + k4 * 4;
                unsigned dr = (unsigned)__cvta_generic_to_shared(
                    &raw[nb * 4096 + edge * 32 + k4 * 4]);
                asm volatile("cp.async.ca.shared.global [%0], [%1], 16;" :: "r"(dr), "l"(g));
            }
            asm volatile("cp.async.commit_group;");
        }

        // --- k-loop: 32 FFMA2 per k per thread ---
        unsigned long long accf[16] = {0}, accs[16] = {0};
#pragma unroll
        for (int k = 0; k < 32; k++) {
            unsigned long long wfp, wsp;
            asm volatile("ld.shared.v2.b64 {%0, %1}, [%2];"
                         : "=l"(wfp), "=l"(wsp) : "r"(bbase + k * 512u));
#pragma unroll
            for (int h = 0; h < 2; h++) {
                unsigned long long ap[8];
                asm volatile("ld.shared.v2.b64 {%0, %1}, [%2];"
                             : "=l"(ap[0]), "=l"(ap[1])
                             : "r"(abase + k * 1024u + h * 64u));
                asm volatile("ld.shared.v2.b64 {%0, %1}, [%2];"
                             : "=l"(ap[2]), "=l"(ap[3])
                             : "r"(abase + k * 1024u + h * 64u + 16u));
                asm volatile("ld.shared.v2.b64 {%0, %1}, [%2];"
                             : "=l"(ap[4]), "=l"(ap[5])
                             : "r"(abase + k * 1024u + h * 64u + 32u));
                asm volatile("ld.shared.v2.b64 {%0, %1}, [%2];"
                             : "=l"(ap[6]), "=l"(ap[7])
                             : "r"(abase + k * 1024u + h * 64u + 48u));
#pragma unroll
                for (int i = 0; i < 8; i++) {
                    asm("fma.rn.f32x2 %0, %1, %2, %3;"
                        : "=l"(accf[h * 8 + i])
                        : "l"(ap[i]), "l"(wfp), "l"(accf[h * 8 + i]));
                    asm("fma.rn.f32x2 %0, %1, %2, %3;"
                        : "=l"(accs[h * 8 + i])
                        : "l"(ap[i]), "l"(wsp), "l"(accs[h * 8 + i]));
                }
            }
        }

        // --- Epilogue: 4 waves of 4 edges ---
        const int* ssrc = &sidx[buf * 256];
        const int* sdst = &sidx[buf * 256 + 128];
#pragma unroll
        for (int w = 0; w < 4; w++) {
            float4 d4[4], s4[4];
            int dsts[4];
#pragma unroll
            for (int i = 0; i < 4; i++) {
                int el = eg * 16 + w * 4 + i;
                dsts[i] = sdst[el];
                int sr = ssrc[el];
                d4[i] = *(const float4*)(ABd + (size_t)dsts[i] * 128 + qc * 4);
                s4[i] = *(const float4*)(ABs + (size_t)sr * 128 + qc * 4);
            }
#pragma unroll
            for (int i = 0; i < 4; i++) {
                int j = w * 4 + i;
                float ef0, ef1, es0, es1;
                asm("mov.b64 {%0, %1}, %2;" : "=f"(ef0), "=f"(ef1) : "l"(accf[j]));
                asm("mov.b64 {%0, %1}, %2;" : "=f"(es0), "=f"(es1) : "l"(accs[j]));
                float pf0 = d4[i].x + s4[i].x + ef0;
                float pf1 = d4[i].y + s4[i].y + ef1;
                float q0  = d4[i].z + s4[i].z + es0;
                float q1  = d4[i].w + s4[i].w + es1;
                float m0 = sigmoidf_(pf0) * softplusf_(q0);
                float m1 = sigmoidf_(pf1) * softplusf_(q1);
                float* outp = hout + (size_t)dsts[i] * 64 + 2 * qc;
                asm volatile("red.global.add.v2.f32 [%0], {%1, %2};"
                             :: "l"(outp), "f"(m0), "f"(m1) : "memory");
            }
        }

        buf ^= 1;
    }
}

// ---------------------------------------------------------------------------
__global__ void init_out_kernel(float* __restrict__ out, const float* __restrict__ b_out)
{
    int t = threadIdx.x;
    if (t < NG) out[t] = b_out[0];
}

__global__ void __launch_bounds__(256) pool_kernel(
    const float* __restrict__ h2, const int* __restrict__ batch,
    const float* __restrict__ Wout, float* __restrict__ out)
{
    const int warp = blockIdx.x * (blockDim.x >> 5) + (threadIdx.x >> 5);
    const int lane = threadIdx.x & 31;
    if (warp >= NN) return;
    float2 v = *(const float2*)(h2 + (size_t)warp * 64 + 2 * lane);
    float s = v.x * Wout[2 * lane] + v.y * Wout[2 * lane + 1];
#pragma unroll
    for (int off = 16; off; off >>= 1)
        s += __shfl_down_sync(0xffffffffu, s, off);
    if (lane == 0) atomicAdd(&out[batch[warp]], s);
}

// ---------------------------------------------------------------------------
extern "C" void kernel_launch(void* const* d_in, const int* in_sizes, int n_in,
                              void* d_out, int out_size)
{
    const float* x     = (const float*)d_in[0];
    const int*   ei    = (const int*)d_in[1];
    const float* ea    = (const float*)d_in[2];
    const int*   batch = (const int*)d_in[3];
    const float* Wf1  = (const float*)d_in[4];
    const float* bf1  = (const float*)d_in[5];
    const float* Ws1  = (const float*)d_in[6];
    const float* bs1  = (const float*)d_in[7];
    const float* Wf2  = (const float*)d_in[8];
    const float* bf2  = (const float*)d_in[9];
    const float* Ws2  = (const float*)d_in[10];
    const float* bs2  = (const float*)d_in[11];
    const float* Wout = (const float*)d_in[12];
    const float* bout = (const float*)d_in[13];
    float* out = (float*)d_out;

    float *ABd, *ABs, *h1, *h2;
    cudaGetSymbolAddress((void**)&ABd, g_ABd);
    cudaGetSymbolAddress((void**)&ABs, g_ABs);
    cudaGetSymbolAddress((void**)&h1, g_h1);
    cudaGetSymbolAddress((void**)&h2, g_h2);

    cudaFuncSetAttribute(edge_gemm_kernel,
                         cudaFuncAttributeMaxDynamicSharedMemorySize,
                         EDGE_SMEM_BYTES);

    const dim3 pgrid((NN + 63) / 64, 4);

    // ---- Layer 1 ----
    proj_kernel<<<pgrid, 256>>>(x, Wf1, Ws1, bf1, bs1, ABd, ABs);
    cudaMemcpyAsync(h1, x, (size_t)NN * DN * sizeof(float),
                    cudaMemcpyDeviceToDevice);
    edge_gemm_kernel<<<EGRID, 256, EDGE_SMEM_BYTES>>>(ei, ea, ABd, ABs, Wf1, Ws1, h1);

    // ---- Layer 2 ----
    proj_kernel<<<pgrid, 256>>>(h1, Wf2, Ws2, bf2, bs2, ABd, ABs);
    cudaMemcpyAsync(h2, h1, (size_t)NN * DN * sizeof(float),
                    cudaMemcpyDeviceToDevice);
    edge_gemm_kernel<<<EGRID, 256, EDGE_SMEM_BYTES>>>(ei, ea, ABd, ABs, Wf2, Ws2, h2);

    // ---- Pool + readout ----
    init_out_kernel<<<1, 512>>>(out, bout);
    pool_kernel<<<NN / 8, 256>>>(h2, batch, Wout, out);
}

// round 13
// speedup vs baseline: 1.0947x; 1.0947x over previous
#include <cuda_runtime.h>
#include <cuda_bf16.h>

#define NN 50000
#define NE 800000
#define NG 512
#define DN 64
#define DE 32
#define ET 64            // edges per block tile -> 12500 blocks

// Scratch (allocation-free: __device__ globals)
// ABd[node][128]: quads {af[2c],af[2c+1],as[2c],as[2c+1]} c=0..31 (dst gather)
// ABs[node][128]: quads {bf[2c],bf[2c+1],bs[2c],bs[2c+1]} c=0..31 (src gather)
__device__ float g_ABd[NN * 128];
__device__ float g_ABs[NN * 128];
__device__ float g_h1[NN * DN];
__device__ float g_h2[NN * DN];

// ---------------------------------------------------------------------------
// Node projection into interleaved gather layout (+ bias fold).
// ---------------------------------------------------------------------------
__global__ void __launch_bounds__(256) proj_kernel(
    const float* __restrict__ h, const float* __restrict__ Wf,
    const float* __restrict__ Ws, const float* __restrict__ bfv,
    const float* __restrict__ bsv, float* __restrict__ ABd,
    float* __restrict__ ABs)
{
    __shared__ float As[64][65];
    __shared__ float Bs[64][64];

    const int tid = threadIdx.x;
    const int node0 = blockIdx.x * 64;
    const int cb = blockIdx.y;

    const float* Wsrc = (cb < 2) ? Wf : Ws;
    const int rowoff = (cb & 1) ? 64 : 0;

#pragma unroll
    for (int t = 0; t < 16; t++) {
        int lin = t * 256 + tid;
        int k = lin >> 6, j = lin & 63;
        Bs[k][j] = Wsrc[(rowoff + k) * 64 + j];
    }
#pragma unroll
    for (int t = 0; t < 16; t++) {
        int lin = t * 256 + tid;
        int n = lin >> 6, k = lin & 63;
        int node = node0 + n;
        As[k][n] = (node < NN) ? h[node * 64 + k] : 0.0f;
    }
    __syncthreads();

    const int tx = tid & 15;
    const int ty = tid >> 4;
    float acc[4][4] = {};

#pragma unroll
    for (int k = 0; k < 64; k++) {
        float4 b4 = *(const float4*)&Bs[k][tx * 4];
        float a0 = As[k][ty * 4 + 0];
        float a1 = As[k][ty * 4 + 1];
        float a2 = As[k][ty * 4 + 2];
        float a3 = As[k][ty * 4 + 3];
        acc[0][0] += a0 * b4.x; acc[0][1] += a0 * b4.y; acc[0][2] += a0 * b4.z; acc[0][3] += a0 * b4.w;
        acc[1][0] += a1 * b4.x; acc[1][1] += a1 * b4.y; acc[1][2] += a1 * b4.z; acc[1][3] += a1 * b4.w;
        acc[2][0] += a2 * b4.x; acc[2][1] += a2 * b4.y; acc[2][2] += a2 * b4.z; acc[2][3] += a2 * b4.w;
        acc[3][0] += a3 * b4.x; acc[3][1] += a3 * b4.y; acc[3][2] += a3 * b4.z; acc[3][3] += a3 * b4.w;
    }

    float bias[4] = {0.f, 0.f, 0.f, 0.f};
    if (cb == 0) {
#pragma unroll
        for (int j = 0; j < 4; j++) bias[j] = bfv[tx * 4 + j];
    } else if (cb == 2) {
#pragma unroll
        for (int j = 0; j < 4; j++) bias[j] = bsv[tx * 4 + j];
    }

    float* outbase = (cb == 0 || cb == 2) ? ABd : ABs;
    const int sub = (cb >= 2) ? 2 : 0;

#pragma unroll
    for (int i = 0; i < 4; i++) {
        int node = node0 + ty * 4 + i;
        if (node < NN) {
            float2 lo = make_float2(acc[i][0] + bias[0], acc[i][1] + bias[1]);
            float2 hi = make_float2(acc[i][2] + bias[2], acc[i][3] + bias[3]);
            *(float2*)&outbase[(size_t)node * 128 + (2 * tx + 0) * 4 + sub] = lo;
            *(float2*)&outbase[(size_t)node * 128 + (2 * tx + 1) * 4 + sub] = hi;
        }
    }
}

// ---------------------------------------------------------------------------
// Edge GEMM kernel: block = 64 edges x 128 outputs (32 quads), K=32.
// 3 blocks/SM (regs capped at 84): thread (qc,eg) owns quad-col qc for 8
// edges. Per k: 1 B load + 4 broadcast A loads + 16 FFMA2.
// ---------------------------------------------------------------------------
__device__ __forceinline__ float sigmoidf_(float x) {
    return 1.0f / (1.0f + __expf(-x));
}
__device__ __forceinline__ float softplusf_(float x) {
    float ax = fabsf(x);
    float em = __expf(-ax);
    return fmaxf(x, 0.0f) + __logf(1.0f + em);
}

__global__ void __launch_bounds__(256, 3) edge_gemm_kernel(
    const int* __restrict__ ei, const float* __restrict__ ea,
    const float* __restrict__ ABd, const float* __restrict__ ABs,
    const float* __restrict__ Wf, const float* __restrict__ Ws,
    float* __restrict__ hout)
{
    __shared__ float Asd[32][128];   // [k][edge-dup]: edge e at floats {2e,2e+1}
    __shared__ float Bq[32][128];    // [k][quad-interleaved weights]
    __shared__ int   ssrc[ET], sdst[ET];

    const int tid = threadIdx.x;
    const int e0 = blockIdx.x * ET;

    // --- Stage edge indices ---
    if (tid < ET) {
        ssrc[tid] = ei[e0 + tid];
        sdst[tid] = ei[NE + e0 + tid];
    }

    // --- Stage ea duplicated: thread t -> edge t>>2, k0 = (t&3)*8 ---
    {
        const int el = tid >> 2;
        const int k0 = (tid & 3) * 8;
        const float* src = ea + (size_t)(e0 + el) * 32 + k0;
        float4 v0 = *(const float4*)(src);
        float4 v1 = *(const float4*)(src + 4);
#pragma unroll
        for (int j = 0; j < 4; j++) {
            float x = (&v0.x)[j];
            *(float2*)&Asd[k0 + j][2 * el] = make_float2(x, x);
        }
#pragma unroll
        for (int j = 0; j < 4; j++) {
            float x = (&v1.x)[j];
            *(float2*)&Asd[k0 + 4 + j][2 * el] = make_float2(x, x);
        }
    }

    // --- Stage quad-interleaved bottom weights: Bq[k][4c+{0,1,2,3}] ---
#pragma unroll
    for (int t = 0; t < 16; t++) {
        int idx = t * 256 + tid;           // 4096 total
        int k = idx >> 7, col = idx & 127;
        int c = col >> 2, sub = col & 3;
        const float* W = (sub < 2) ? Wf : Ws;
        Bq[k][col] = W[(size_t)(128 + k) * 64 + 2 * c + (sub & 1)];
    }
    __syncthreads();

    const int qc = tid & 31;   // quad column 0..31
    const int eg = tid >> 5;   // edge group: edges eg*8 .. +7

    const unsigned abase = (unsigned)__cvta_generic_to_shared(&Asd[0][eg * 16]);
    const unsigned bbase = (unsigned)__cvta_generic_to_shared(&Bq[0][qc * 4]);

    unsigned long long accf[8] = {0}, accs[8] = {0};

#pragma unroll
    for (int k = 0; k < 32; k++) {
        unsigned long long wfp, wsp;
        asm volatile("ld.shared.v2.b64 {%0, %1}, [%2];"
                     : "=l"(wfp), "=l"(wsp) : "r"(bbase + k * 512u));
        // Two halves of 4 edges to cap transient register pressure
#pragma unroll
        for (int h = 0; h < 2; h++) {
            unsigned long long ap[4];
            asm volatile("ld.shared.v2.b64 {%0, %1}, [%2];"
                         : "=l"(ap[0]), "=l"(ap[1])
                         : "r"(abase + k * 512u + h * 32u));
            asm volatile("ld.shared.v2.b64 {%0, %1}, [%2];"
                         : "=l"(ap[2]), "=l"(ap[3])
                         : "r"(abase + k * 512u + h * 32u + 16u));
#pragma unroll
            for (int i = 0; i < 4; i++) {
                asm("fma.rn.f32x2 %0, %1, %2, %3;"
                    : "=l"(accf[h * 4 + i])
                    : "l"(ap[i]), "l"(wfp), "l"(accf[h * 4 + i]));
                asm("fma.rn.f32x2 %0, %1, %2, %3;"
                    : "=l"(accs[h * 4 + i])
                    : "l"(ap[i]), "l"(wsp), "l"(accs[h * 4 + i]));
            }
        }
    }

    // --- Epilogue: 2 waves of 4 edges ---
#pragma unroll
    for (int w = 0; w < 2; w++) {
        float4 d4[4], s4[4];
        int dsts[4];
#pragma unroll
        for (int i = 0; i < 4; i++) {
            int el = eg * 8 + w * 4 + i;
            dsts[i] = sdst[el];
            int sr = ssrc[el];
            d4[i] = *(const float4*)(ABd + (size_t)dsts[i] * 128 + qc * 4);
            s4[i] = *(const float4*)(ABs + (size_t)sr * 128 + qc * 4);
        }
#pragma unroll
        for (int i = 0; i < 4; i++) {
            int j = w * 4 + i;
            float ef0, ef1, es0, es1;
            asm("mov.b64 {%0, %1}, %2;" : "=f"(ef0), "=f"(ef1) : "l"(accf[j]));
            asm("mov.b64 {%0, %1}, %2;" : "=f"(es0), "=f"(es1) : "l"(accs[j]));
            float pf0 = d4[i].x + s4[i].x + ef0;
            float pf1 = d4[i].y + s4[i].y + ef1;
            float q0  = d4[i].z + s4[i].z + es0;
            float q1  = d4[i].w + s4[i].w + es1;
            float m0 = sigmoidf_(pf0) * softplusf_(q0);
            float m1 = sigmoidf_(pf1) * softplusf_(q1);
            float* outp = hout + (size_t)dsts[i] * 64 + 2 * qc;
            asm volatile("red.global.add.v2.f32 [%0], {%1, %2};"
                         :: "l"(outp), "f"(m0), "f"(m1) : "memory");
        }
    }
}

// ---------------------------------------------------------------------------
__global__ void init_out_kernel(float* __restrict__ out, const float* __restrict__ b_out)
{
    int t = threadIdx.x;
    if (t < NG) out[t] = b_out[0];
}

__global__ void __launch_bounds__(256) pool_kernel(
    const float* __restrict__ h2, const int* __restrict__ batch,
    const float* __restrict__ Wout, float* __restrict__ out)
{
    const int warp = blockIdx.x * (blockDim.x >> 5) + (threadIdx.x >> 5);
    const int lane = threadIdx.x & 31;
    if (warp >= NN) return;
    float2 v = *(const float2*)(h2 + (size_t)warp * 64 + 2 * lane);
    float s = v.x * Wout[2 * lane] + v.y * Wout[2 * lane + 1];
#pragma unroll
    for (int off = 16; off; off >>= 1)
        s += __shfl_down_sync(0xffffffffu, s, off);
    if (lane == 0) atomicAdd(&out[batch[warp]], s);
}

// ---------------------------------------------------------------------------
extern "C" void kernel_launch(void* const* d_in, const int* in_sizes, int n_in,
                              void* d_out, int out_size)
{
    const float* x     = (const float*)d_in[0];
    const int*   ei    = (const int*)d_in[1];
    const float* ea    = (const float*)d_in[2];
    const int*   batch = (const int*)d_in[3];
    const float* Wf1  = (const float*)d_in[4];
    const float* bf1  = (const float*)d_in[5];
    const float* Ws1  = (const float*)d_in[6];
    const float* bs1  = (const float*)d_in[7];
    const float* Wf2  = (const float*)d_in[8];
    const float* bf2  = (const float*)d_in[9];
    const float* Ws2  = (const float*)d_in[10];
    const float* bs2  = (const float*)d_in[11];
    const float* Wout = (const float*)d_in[12];
    const float* bout = (const float*)d_in[13];
    float* out = (float*)d_out;

    float *ABd, *ABs, *h1, *h2;
    cudaGetSymbolAddress((void**)&ABd, g_ABd);
    cudaGetSymbolAddress((void**)&ABs, g_ABs);
    cudaGetSymbolAddress((void**)&h1, g_h1);
    cudaGetSymbolAddress((void**)&h2, g_h2);

    const dim3 pgrid((NN + 63) / 64, 4);
    const int egrid = NE / ET;   // 12500

    // ---- Layer 1 ----
    proj_kernel<<<pgrid, 256>>>(x, Wf1, Ws1, bf1, bs1, ABd, ABs);
    cudaMemcpyAsync(h1, x, (size_t)NN * DN * sizeof(float),
                    cudaMemcpyDeviceToDevice);
    edge_gemm_kernel<<<egrid, 256>>>(ei, ea, ABd, ABs, Wf1, Ws1, h1);

    // ---- Layer 2 ----
    proj_kernel<<<pgrid, 256>>>(h1, Wf2, Ws2, bf2, bs2, ABd, ABs);
    cudaMemcpyAsync(h2, h1, (size_t)NN * DN * sizeof(float),
                    cudaMemcpyDeviceToDevice);
    edge_gemm_kernel<<<egrid, 256>>>(ei, ea, ABd, ABs, Wf2, Ws2, h2);

    // ---- Pool + readout ----
    init_out_kernel<<<1, 512>>>(out, bout);
    pool_kernel<<<NN / 8, 256>>>(h2, batch, Wout, out);
}